// round 2
// baseline (speedup 1.0000x reference)
#include <cuda_runtime.h>
#include <math.h>

// Problem constants: B=4, T=1024, E=1024, H=16, KVH=8, HD=32, N_REP=2
// LAMBDA_INIT = 0.8 - 0.6*exp(-3.6)
#define LAMBDA_INIT_F 0.7836057665316245f
#define ONE_MINUS_LI  0.2163942334683755f
#define QK_SCALE      0.17677669529663687f   // 1/sqrt(32)

// Scratch (device globals — no allocation allowed)
__device__ float g_qkv[4096 * 2048];   // cols [0,1024)=q, [1024,1536)=k, [1536,2048)=v
__device__ float g_attn[4096 * 1024];  // post diff-attn + RMS, pre-Wo
__device__ float g_lambda;

// ---------------------------------------------------------------------------
// lambda_full = exp(sum lq1*lk1) - exp(sum lq2*lk2) + LAMBDA_INIT
// ---------------------------------------------------------------------------
__global__ void lambda_kernel(const float* __restrict__ lq1, const float* __restrict__ lk1,
                              const float* __restrict__ lq2, const float* __restrict__ lk2) {
    int l = threadIdx.x;           // 32 threads
    float a = lq1[l] * lk1[l];
    float b = lq2[l] * lk2[l];
    #pragma unroll
    for (int o = 16; o; o >>= 1) {
        a += __shfl_xor_sync(0xffffffffu, a, o);
        b += __shfl_xor_sync(0xffffffffu, b, o);
    }
    if (l == 0) g_lambda = expf(a) - expf(b) + LAMBDA_INIT_F;
}

// ---------------------------------------------------------------------------
// GEMM 1: g_qkv[4096,2048] = X[4096,1024] @ [Wq | Wk | Wv]
// 128x128 tile, BK=8, 256 threads, 8x8 per thread, fp32
// ---------------------------------------------------------------------------
__global__ __launch_bounds__(256) void gemm_qkv(const float* __restrict__ X,
                                                const float* __restrict__ Wq,
                                                const float* __restrict__ Wk,
                                                const float* __restrict__ Wv) {
    __shared__ float As[8 * 128];
    __shared__ float Bs[8 * 128];
    const int t  = threadIdx.x;
    const int m0 = blockIdx.y * 128;
    const int nt = blockIdx.x;     // 0..15 -> 8 Wq tiles, 4 Wk, 4 Wv

    const float* Wsel; int ldB, c0;
    if (nt < 8)       { Wsel = Wq; ldB = 1024; c0 = nt * 128; }
    else if (nt < 12) { Wsel = Wk; ldB = 512;  c0 = (nt - 8) * 128; }
    else              { Wsel = Wv; ldB = 512;  c0 = (nt - 12) * 128; }

    const int arow = t >> 1, ac4 = (t & 1) * 4;
    const int brow = t >> 5, bc4 = (t & 31) * 4;
    const int ty = t >> 4, tx = t & 15;

    float acc[8][8];
    #pragma unroll
    for (int i = 0; i < 8; i++)
        #pragma unroll
        for (int j = 0; j < 8; j++) acc[i][j] = 0.f;

    for (int k0 = 0; k0 < 1024; k0 += 8) {
        float4 av = *(const float4*)&X[(m0 + arow) * 1024 + k0 + ac4];
        float4 bv = *(const float4*)&Wsel[(k0 + brow) * ldB + c0 + bc4];
        As[(ac4 + 0) * 128 + arow] = av.x;
        As[(ac4 + 1) * 128 + arow] = av.y;
        As[(ac4 + 2) * 128 + arow] = av.z;
        As[(ac4 + 3) * 128 + arow] = av.w;
        *(float4*)&Bs[brow * 128 + bc4] = bv;
        __syncthreads();
        #pragma unroll
        for (int kk = 0; kk < 8; kk++) {
            float4 a0 = *(const float4*)&As[kk * 128 + ty * 8];
            float4 a1 = *(const float4*)&As[kk * 128 + ty * 8 + 4];
            float4 b0 = *(const float4*)&Bs[kk * 128 + tx * 8];
            float4 b1 = *(const float4*)&Bs[kk * 128 + tx * 8 + 4];
            float ar[8] = {a0.x, a0.y, a0.z, a0.w, a1.x, a1.y, a1.z, a1.w};
            float br[8] = {b0.x, b0.y, b0.z, b0.w, b1.x, b1.y, b1.z, b1.w};
            #pragma unroll
            for (int i = 0; i < 8; i++)
                #pragma unroll
                for (int j = 0; j < 8; j++) acc[i][j] += ar[i] * br[j];
        }
        __syncthreads();
    }
    const int cgl = nt * 128 + tx * 8;
    #pragma unroll
    for (int i = 0; i < 8; i++) {
        float4 v0 = {acc[i][0], acc[i][1], acc[i][2], acc[i][3]};
        float4 v1 = {acc[i][4], acc[i][5], acc[i][6], acc[i][7]};
        *(float4*)&g_qkv[(m0 + ty * 8 + i) * 2048 + cgl]     = v0;
        *(float4*)&g_qkv[(m0 + ty * 8 + i) * 2048 + cgl + 4] = v1;
    }
}

// ---------------------------------------------------------------------------
// GEMM 2: out[4096,1024] = g_attn[4096,1024] @ Wo[1024,1024]
// ---------------------------------------------------------------------------
__global__ __launch_bounds__(256) void gemm_out(const float* __restrict__ Wo,
                                                float* __restrict__ out) {
    __shared__ float As[8 * 128];
    __shared__ float Bs[8 * 128];
    const int t  = threadIdx.x;
    const int m0 = blockIdx.y * 128;
    const int n0 = blockIdx.x * 128;

    const int arow = t >> 1, ac4 = (t & 1) * 4;
    const int brow = t >> 5, bc4 = (t & 31) * 4;
    const int ty = t >> 4, tx = t & 15;

    float acc[8][8];
    #pragma unroll
    for (int i = 0; i < 8; i++)
        #pragma unroll
        for (int j = 0; j < 8; j++) acc[i][j] = 0.f;

    for (int k0 = 0; k0 < 1024; k0 += 8) {
        float4 av = *(const float4*)&g_attn[(m0 + arow) * 1024 + k0 + ac4];
        float4 bv = *(const float4*)&Wo[(k0 + brow) * 1024 + n0 + bc4];
        As[(ac4 + 0) * 128 + arow] = av.x;
        As[(ac4 + 1) * 128 + arow] = av.y;
        As[(ac4 + 2) * 128 + arow] = av.z;
        As[(ac4 + 3) * 128 + arow] = av.w;
        *(float4*)&Bs[brow * 128 + bc4] = bv;
        __syncthreads();
        #pragma unroll
        for (int kk = 0; kk < 8; kk++) {
            float4 a0 = *(const float4*)&As[kk * 128 + ty * 8];
            float4 a1 = *(const float4*)&As[kk * 128 + ty * 8 + 4];
            float4 b0 = *(const float4*)&Bs[kk * 128 + tx * 8];
            float4 b1 = *(const float4*)&Bs[kk * 128 + tx * 8 + 4];
            float ar[8] = {a0.x, a0.y, a0.z, a0.w, a1.x, a1.y, a1.z, a1.w};
            float br[8] = {b0.x, b0.y, b0.z, b0.w, b1.x, b1.y, b1.z, b1.w};
            #pragma unroll
            for (int i = 0; i < 8; i++)
                #pragma unroll
                for (int j = 0; j < 8; j++) acc[i][j] += ar[i] * br[j];
        }
        __syncthreads();
    }
    #pragma unroll
    for (int i = 0; i < 8; i++) {
        float4 v0 = {acc[i][0], acc[i][1], acc[i][2], acc[i][3]};
        float4 v1 = {acc[i][4], acc[i][5], acc[i][6], acc[i][7]};
        *(float4*)&out[(m0 + ty * 8 + i) * 1024 + n0 + tx * 8]     = v0;
        *(float4*)&out[(m0 + ty * 8 + i) * 1024 + n0 + tx * 8 + 4] = v1;
    }
}

// ---------------------------------------------------------------------------
// RoPE in place on q cols [0,1024) (32 heads x 32) and k cols [1024,1536)
// (16 heads x 32). pairs (j, j+16), angle = t * 10000^{-j/16}
// ---------------------------------------------------------------------------
__global__ __launch_bounds__(256) void rope_kernel() {
    const int row = blockIdx.x;      // 0..4095
    const int t   = row & 1023;
    __shared__ double invf[16];
    if (threadIdx.x < 16)
        invf[threadIdx.x] = pow(10000.0, -(double)threadIdx.x / 16.0);
    __syncthreads();

    for (int i = threadIdx.x; i < 768; i += 256) {   // 48 heads * 16 pairs
        int head = i >> 4;
        int p    = i & 15;
        int base = (head < 32) ? head * 32 : 1024 + (head - 32) * 32;
        float* ptr = &g_qkv[row * 2048 + base + p];
        double ang = (double)t * invf[p];
        double r   = fmod(ang, 6.283185307179586);
        float s, c;
        sincosf((float)r, &s, &c);
        float x1 = ptr[0], x2 = ptr[16];
        ptr[0]  = x1 * c + x2 * s;
        ptr[16] = x2 * c - x1 * s;
    }
}

// ---------------------------------------------------------------------------
// Fused differential attention + RMS norm.
// Block: (qt, bh) = 64 queries of one (b,h). 256 threads.
// Two softmax streams (q1k1, q2k2) over shared V (64-dim), online softmax,
// 32-key chunks. P overwrites K smem region after score phase.
// ---------------------------------------------------------------------------
__global__ __launch_bounds__(256) void attn_kernel(const float* __restrict__ rms_w) {
    const int qt = blockIdx.x;       // 0..15
    const int bh = blockIdx.y;       // 0..63
    const int b  = bh >> 4, h = bh & 15;
    const int kh = h >> 1;
    const int tid = threadIdx.x;

    __shared__ float sQ1[64 * 32], sQ2[64 * 32];
    __shared__ float sV[32 * 64];
    __shared__ float sKP[4096];      // K1[1024] K2[1024] during scores; P1[2048] P2[2048] after
    __shared__ float sM1[64], sL1[64], sC1[64], sM2[64], sL2[64], sC2[64];

    const int rowBase = b * 1024 + qt * 64;

    // Load Q tiles (scaled by 1/sqrt(HD))
    for (int i = tid; i < 512; i += 256) {
        int q  = i >> 3;
        int d4 = (i & 7) << 2;
        const float* src = &g_qkv[(rowBase + q) * 2048 + h * 64 + d4];
        float4 v1 = *(const float4*)src;
        float4 v2 = *(const float4*)(src + 32);
        v1.x *= QK_SCALE; v1.y *= QK_SCALE; v1.z *= QK_SCALE; v1.w *= QK_SCALE;
        v2.x *= QK_SCALE; v2.y *= QK_SCALE; v2.z *= QK_SCALE; v2.w *= QK_SCALE;
        *(float4*)&sQ1[q * 32 + d4] = v1;
        *(float4*)&sQ2[q * 32 + d4] = v2;
    }
    if (tid < 64) { sM1[tid] = -1e30f; sL1[tid] = 0.f; sM2[tid] = -1e30f; sL2[tid] = 0.f; }
    __syncthreads();

    const int qg = tid >> 4;   // row group: rows qg*4 + i
    const int kg = tid & 15;   // score cols kg*2+j   /  PV dims kg*4+j

    float o1[4][4], o2[4][4];
    #pragma unroll
    for (int i = 0; i < 4; i++)
        #pragma unroll
        for (int j = 0; j < 4; j++) { o1[i][j] = 0.f; o2[i][j] = 0.f; }

    const int nch = 2 * qt + 2;
    for (int c = 0; c < nch; ++c) {
        const int kb = c << 5;

        // Load K1,K2 (into sKP) and V chunk
        for (int i = tid; i < 1024; i += 256) {
            if (i < 512) {
                int s  = i >> 8;            // 0:K1, 1:K2
                int ii = i & 255;
                int j  = ii >> 3, d4 = (ii & 7) << 2;
                float4 v = *(const float4*)&g_qkv[(b * 1024 + kb + j) * 2048 + 1024 + kh * 64 + s * 32 + d4];
                *(float4*)&sKP[s * 1024 + j * 32 + d4] = v;
            } else {
                int ii = i - 512;
                int j  = ii >> 4, d4 = (ii & 15) << 2;
                float4 v = *(const float4*)&g_qkv[(b * 1024 + kb + j) * 2048 + 1536 + kh * 64 + d4];
                *(float4*)&sV[j * 64 + d4] = v;
            }
        }
        __syncthreads();

        // Scores: 4q x 2k per thread, both streams
        float s1[4][2], s2[4][2];
        #pragma unroll
        for (int i = 0; i < 4; i++) { s1[i][0] = s1[i][1] = 0.f; s2[i][0] = s2[i][1] = 0.f; }

        const float4* Q1f = (const float4*)sQ1;
        const float4* Q2f = (const float4*)sQ2;
        const float4* K1f = (const float4*)sKP;
        const float4* K2f = (const float4*)(sKP + 1024);
        #pragma unroll
        for (int dd = 0; dd < 8; ++dd) {
            float4 ka = K1f[(kg * 2 + 0) * 8 + dd];
            float4 kb4 = K1f[(kg * 2 + 1) * 8 + dd];
            #pragma unroll
            for (int i = 0; i < 4; i++) {
                float4 qv = Q1f[(qg * 4 + i) * 8 + dd];
                s1[i][0] += qv.x * ka.x + qv.y * ka.y + qv.z * ka.z + qv.w * ka.w;
                s1[i][1] += qv.x * kb4.x + qv.y * kb4.y + qv.z * kb4.z + qv.w * kb4.w;
            }
            float4 kc = K2f[(kg * 2 + 0) * 8 + dd];
            float4 kd = K2f[(kg * 2 + 1) * 8 + dd];
            #pragma unroll
            for (int i = 0; i < 4; i++) {
                float4 qv = Q2f[(qg * 4 + i) * 8 + dd];
                s2[i][0] += qv.x * kc.x + qv.y * kc.y + qv.z * kc.z + qv.w * kc.w;
                s2[i][1] += qv.x * kd.x + qv.y * kd.y + qv.z * kd.z + qv.w * kd.w;
            }
        }
        __syncthreads();    // K reads complete before P overwrites sKP

        // Online softmax per row (16 threads per row, half-warp shuffles)
        const bool maskCh = (c >= 2 * qt);
        #pragma unroll
        for (int i = 0; i < 4; i++) {
            const int q  = qg * 4 + i;
            const int qa = qt * 64 + q;
            if (maskCh) {
                if (kb + kg * 2 + 0 > qa) { s1[i][0] = -1e30f; s2[i][0] = -1e30f; }
                if (kb + kg * 2 + 1 > qa) { s1[i][1] = -1e30f; s2[i][1] = -1e30f; }
            }
            // stream 1
            {
                float mOld = sM1[q];
                float ml = fmaxf(s1[i][0], s1[i][1]);
                #pragma unroll
                for (int o = 8; o; o >>= 1) ml = fmaxf(ml, __shfl_xor_sync(0xffffffffu, ml, o));
                float mNew = fmaxf(mOld, ml);
                float p0 = expf(s1[i][0] - mNew);
                float p1 = expf(s1[i][1] - mNew);
                float ls = p0 + p1;
                #pragma unroll
                for (int o = 8; o; o >>= 1) ls += __shfl_xor_sync(0xffffffffu, ls, o);
                sKP[q * 32 + kg * 2 + 0] = p0;
                sKP[q * 32 + kg * 2 + 1] = p1;
                if (kg == 0) {
                    float cc = expf(mOld - mNew);
                    sC1[q] = cc; sM1[q] = mNew; sL1[q] = sL1[q] * cc + ls;
                }
            }
            // stream 2
            {
                float mOld = sM2[q];
                float ml = fmaxf(s2[i][0], s2[i][1]);
                #pragma unroll
                for (int o = 8; o; o >>= 1) ml = fmaxf(ml, __shfl_xor_sync(0xffffffffu, ml, o));
                float mNew = fmaxf(mOld, ml);
                float p0 = expf(s2[i][0] - mNew);
                float p1 = expf(s2[i][1] - mNew);
                float ls = p0 + p1;
                #pragma unroll
                for (int o = 8; o; o >>= 1) ls += __shfl_xor_sync(0xffffffffu, ls, o);
                sKP[2048 + q * 32 + kg * 2 + 0] = p0;
                sKP[2048 + q * 32 + kg * 2 + 1] = p1;
                if (kg == 0) {
                    float cc = expf(mOld - mNew);
                    sC2[q] = cc; sM2[q] = mNew; sL2[q] = sL2[q] * cc + ls;
                }
            }
        }
        __syncthreads();

        // PV: rescale accumulators, then O += P * V (4q x 4d per thread)
        #pragma unroll
        for (int i = 0; i < 4; i++) {
            const int q = qg * 4 + i;
            float c1 = sC1[q], c2 = sC2[q];
            #pragma unroll
            for (int j = 0; j < 4; j++) { o1[i][j] *= c1; o2[i][j] *= c2; }
        }
        #pragma unroll 4
        for (int k = 0; k < 32; k++) {
            float4 vv = *(const float4*)&sV[k * 64 + kg * 4];
            #pragma unroll
            for (int i = 0; i < 4; i++) {
                float p1v = sKP[(qg * 4 + i) * 32 + k];
                float p2v = sKP[2048 + (qg * 4 + i) * 32 + k];
                o1[i][0] += p1v * vv.x; o1[i][1] += p1v * vv.y;
                o1[i][2] += p1v * vv.z; o1[i][3] += p1v * vv.w;
                o2[i][0] += p2v * vv.x; o2[i][1] += p2v * vv.y;
                o2[i][2] += p2v * vv.z; o2[i][3] += p2v * vv.w;
            }
        }
        __syncthreads();   // done with P/V before next chunk load
    }

    // Epilogue: diff, RMS norm over 64 dims, weight, scale; write g_attn
    const float lam = g_lambda;
    const float4 wv = *(const float4*)&rms_w[kg * 4];
    #pragma unroll
    for (int i = 0; i < 4; i++) {
        const int q = qg * 4 + i;
        float inv1 = 1.f / sL1[q];
        float inv2 = lam / sL2[q];
        float a0 = o1[i][0] * inv1 - o2[i][0] * inv2;
        float a1 = o1[i][1] * inv1 - o2[i][1] * inv2;
        float a2 = o1[i][2] * inv1 - o2[i][2] * inv2;
        float a3 = o1[i][3] * inv1 - o2[i][3] * inv2;
        float ssq = a0 * a0 + a1 * a1 + a2 * a2 + a3 * a3;
        #pragma unroll
        for (int o = 8; o; o >>= 1) ssq += __shfl_xor_sync(0xffffffffu, ssq, o);
        float invr = rsqrtf(ssq * (1.0f / 64.0f) + 1e-6f) * ONE_MINUS_LI;
        float4 outv = { a0 * invr * wv.x, a1 * invr * wv.y,
                        a2 * invr * wv.z, a3 * invr * wv.w };
        *(float4*)&g_attn[(rowBase + q) * 1024 + h * 64 + kg * 4] = outv;
    }
}

// ---------------------------------------------------------------------------
extern "C" void kernel_launch(void* const* d_in, const int* in_sizes, int n_in,
                              void* d_out, int out_size) {
    (void)in_sizes; (void)n_in; (void)out_size;
    const float* x   = (const float*)d_in[0];
    const float* Wq  = (const float*)d_in[1];
    const float* Wk  = (const float*)d_in[2];
    const float* Wv  = (const float*)d_in[3];
    const float* Wo  = (const float*)d_in[4];
    const float* lq1 = (const float*)d_in[5];
    const float* lk1 = (const float*)d_in[6];
    const float* lq2 = (const float*)d_in[7];
    const float* lk2 = (const float*)d_in[8];
    const float* rw  = (const float*)d_in[9];
    float* out = (float*)d_out;

    lambda_kernel<<<1, 32>>>(lq1, lk1, lq2, lk2);
    gemm_qkv<<<dim3(16, 32), 256>>>(x, Wq, Wk, Wv);
    rope_kernel<<<4096, 256>>>();
    attn_kernel<<<dim3(16, 64), 256>>>(rw);
    gemm_out<<<dim3(8, 32), 256>>>(Wo, out);
}

// round 3
// speedup vs baseline: 1.3210x; 1.3210x over previous
#include <cuda_runtime.h>
#include <math.h>
#include <stdint.h>

// Problem constants: B=4, T=1024, E=1024, H=16, KVH=8, HD=32, N_REP=2
#define LAMBDA_INIT_F 0.7836057665316245f
#define ONE_MINUS_LI  0.2163942334683755f
#define QK_SCALE      0.17677669529663687f   // 1/sqrt(32)

// Scratch (device globals — no allocation allowed)
__device__ float g_qkv[4096 * 2048];   // cols [0,1024)=q, [1024,1536)=k, [1536,2048)=v
__device__ float g_attn[4096 * 1024];  // post diff-attn + RMS, pre-Wo
__device__ float g_lambda;

// ---------------------------------------------------------------------------
__global__ void lambda_kernel(const float* __restrict__ lq1, const float* __restrict__ lk1,
                              const float* __restrict__ lq2, const float* __restrict__ lk2) {
    int l = threadIdx.x;
    float a = lq1[l] * lk1[l];
    float b = lq2[l] * lk2[l];
    #pragma unroll
    for (int o = 16; o; o >>= 1) {
        a += __shfl_xor_sync(0xffffffffu, a, o);
        b += __shfl_xor_sync(0xffffffffu, b, o);
    }
    if (l == 0) g_lambda = expf(a) - expf(b) + LAMBDA_INIT_F;
}

// ---------------------------------------------------------------------------
// TF32 tensor-core GEMM building block: C[128,128] tile, K=1024, BK=32.
// 256 threads = 8 warps in 2x4; warp tile 64x32 via m16n8k8 (4 mt x 4 nt).
// A smem k-major ld=137 (conflict-free stores, ~2-way-max frag loads).
// B smem k-major ld=136 (conflict-free both ways).
// ---------------------------------------------------------------------------
__device__ __forceinline__ float ftf32(float x) {
    uint32_t u;
    asm("cvt.rna.tf32.f32 %0, %1;" : "=r"(u) : "f"(x));
    return __uint_as_float(u);
}

#define MMA_TF32(c, a, b)                                              \
    asm volatile(                                                      \
        "mma.sync.aligned.m16n8k8.row.col.f32.tf32.tf32.f32 "          \
        "{%0,%1,%2,%3}, {%4,%5,%6,%7}, {%8,%9}, {%0,%1,%2,%3};"        \
        : "+f"((c)[0]), "+f"((c)[1]), "+f"((c)[2]), "+f"((c)[3])       \
        : "r"((a)[0]), "r"((a)[1]), "r"((a)[2]), "r"((a)[3]),          \
          "r"((b)[0]), "r"((b)[1]))

#define LDA_S 137
#define LDB_S 136

__device__ __forceinline__ void gemm128_tf32_body(
    float* __restrict__ As, float* __restrict__ Bs,
    const float* __restrict__ A, int lda, int m0,
    const float* __restrict__ B, int ldb, int bcol0,
    float* __restrict__ C, int ldc, int ccol0)
{
    const int t    = threadIdx.x;
    const int lane = t & 31, wid = t >> 5;
    const int wm   = (wid >> 2) * 64;
    const int wn   = (wid & 3) * 32;
    const int g    = lane >> 2, tig = lane & 3;

    // loader indices (fixed per thread)
    const int arow = t >> 3;            // +128*hi  (two sub-iterations of 128 rows? no: idx form)
    (void)arow;

    float acc[4][4][4];
    #pragma unroll
    for (int mt = 0; mt < 4; mt++)
        #pragma unroll
        for (int nt = 0; nt < 4; nt++)
            #pragma unroll
            for (int i = 0; i < 4; i++) acc[mt][nt][i] = 0.f;

    float4 pa[4], pb[4];
    // prefetch k0 = 0
    #pragma unroll
    for (int i = 0; i < 4; i++) {
        int idx = t + (i << 8);
        int ar  = idx >> 3, ak = (idx & 7) << 2;
        pa[i] = *(const float4*)&A[(m0 + ar) * lda + ak];
        int bkr = idx >> 5, bc4 = (idx & 31) << 2;
        pb[i] = *(const float4*)&B[bkr * ldb + bcol0 + bc4];
    }

    for (int k0 = 0; k0 < 1024; k0 += 32) {
        // commit prefetched tile to smem (with tf32 rounding)
        #pragma unroll
        for (int i = 0; i < 4; i++) {
            int idx = t + (i << 8);
            int ar  = idx >> 3, ak = (idx & 7) << 2;
            As[(ak + 0) * LDA_S + ar] = ftf32(pa[i].x);
            As[(ak + 1) * LDA_S + ar] = ftf32(pa[i].y);
            As[(ak + 2) * LDA_S + ar] = ftf32(pa[i].z);
            As[(ak + 3) * LDA_S + ar] = ftf32(pa[i].w);
            int bkr = idx >> 5, bc4 = (idx & 31) << 2;
            float4 w4 = { ftf32(pb[i].x), ftf32(pb[i].y), ftf32(pb[i].z), ftf32(pb[i].w) };
            *(float4*)&Bs[bkr * LDB_S + bc4] = w4;
        }
        __syncthreads();

        if (k0 + 32 < 1024) {
            int kn = k0 + 32;
            #pragma unroll
            for (int i = 0; i < 4; i++) {
                int idx = t + (i << 8);
                int ar  = idx >> 3, ak = (idx & 7) << 2;
                pa[i] = *(const float4*)&A[(m0 + ar) * lda + kn + ak];
                int bkr = idx >> 5, bc4 = (idx & 31) << 2;
                pb[i] = *(const float4*)&B[(kn + bkr) * ldb + bcol0 + bc4];
            }
        }

        #pragma unroll
        for (int kk = 0; kk < 32; kk += 8) {
            uint32_t af[4][4], bf[4][2];
            #pragma unroll
            for (int mt = 0; mt < 4; mt++) {
                int rb = wm + mt * 16 + g;
                const float* a0p = &As[(kk + tig) * LDA_S + rb];
                const float* a1p = &As[(kk + tig + 4) * LDA_S + rb];
                af[mt][0] = __float_as_uint(a0p[0]);
                af[mt][1] = __float_as_uint(a0p[8]);
                af[mt][2] = __float_as_uint(a1p[0]);
                af[mt][3] = __float_as_uint(a1p[8]);
            }
            #pragma unroll
            for (int nt = 0; nt < 4; nt++) {
                int cb = wn + nt * 8 + g;
                bf[nt][0] = __float_as_uint(Bs[(kk + tig) * LDB_S + cb]);
                bf[nt][1] = __float_as_uint(Bs[(kk + tig + 4) * LDB_S + cb]);
            }
            #pragma unroll
            for (int mt = 0; mt < 4; mt++)
                #pragma unroll
                for (int nt = 0; nt < 4; nt++)
                    MMA_TF32(acc[mt][nt], af[mt], bf[nt]);
        }
        __syncthreads();
    }

    // epilogue: fragment layout rows g / g+8, cols 2*tig, 2*tig+1
    #pragma unroll
    for (int mt = 0; mt < 4; mt++) {
        #pragma unroll
        for (int nt = 0; nt < 4; nt++) {
            int r  = m0 + wm + mt * 16 + g;
            int cg = ccol0 + wn + nt * 8 + (tig << 1);
            float2 v0 = { acc[mt][nt][0], acc[mt][nt][1] };
            float2 v1 = { acc[mt][nt][2], acc[mt][nt][3] };
            *(float2*)&C[r * ldc + cg]       = v0;
            *(float2*)&C[(r + 8) * ldc + cg] = v1;
        }
    }
}

// GEMM 1: g_qkv[4096,2048] = X @ [Wq | Wk | Wv]
__global__ __launch_bounds__(256) void gemm_qkv_tc(const float* __restrict__ X,
                                                   const float* __restrict__ Wq,
                                                   const float* __restrict__ Wk,
                                                   const float* __restrict__ Wv) {
    __shared__ float As[32 * LDA_S];
    __shared__ float Bs[32 * LDB_S];
    const int m0 = blockIdx.y * 128;
    const int nt = blockIdx.x;     // 0..15
    const float* Bsel; int ldb, bcol0, ccol0;
    if (nt < 8)       { Bsel = Wq; ldb = 1024; bcol0 = nt * 128;        ccol0 = nt * 128; }
    else if (nt < 12) { Bsel = Wk; ldb = 512;  bcol0 = (nt - 8) * 128;  ccol0 = 1024 + (nt - 8) * 128; }
    else              { Bsel = Wv; ldb = 512;  bcol0 = (nt - 12) * 128; ccol0 = 1536 + (nt - 12) * 128; }
    gemm128_tf32_body(As, Bs, X, 1024, m0, Bsel, ldb, bcol0, g_qkv, 2048, ccol0);
}

// GEMM 2: out[4096,1024] = g_attn @ Wo
__global__ __launch_bounds__(256) void gemm_out_tc(const float* __restrict__ Wo,
                                                   float* __restrict__ out) {
    __shared__ float As[32 * LDA_S];
    __shared__ float Bs[32 * LDB_S];
    const int m0 = blockIdx.y * 128;
    const int n0 = blockIdx.x * 128;
    gemm128_tf32_body(As, Bs, g_attn, 1024, m0, Wo, 1024, n0, out, 1024, n0);
}

// ---------------------------------------------------------------------------
// RoPE in place on q cols [0,1024) (32 heads x 32) and k cols [1024,1536)
// ---------------------------------------------------------------------------
__global__ __launch_bounds__(256) void rope_kernel() {
    const int row = blockIdx.x;      // 0..4095
    const int t   = row & 1023;
    __shared__ double invf[16];
    if (threadIdx.x < 16)
        invf[threadIdx.x] = pow(10000.0, -(double)threadIdx.x / 16.0);
    __syncthreads();

    for (int i = threadIdx.x; i < 768; i += 256) {   // 48 heads * 16 pairs
        int head = i >> 4;
        int p    = i & 15;
        int base = (head < 32) ? head * 32 : 1024 + (head - 32) * 32;
        float* ptr = &g_qkv[row * 2048 + base + p];
        double ang = (double)t * invf[p];
        double r   = fmod(ang, 6.283185307179586);
        float s, c;
        sincosf((float)r, &s, &c);
        float x1 = ptr[0], x2 = ptr[16];
        ptr[0]  = x1 * c + x2 * s;
        ptr[16] = x2 * c - x1 * s;
    }
}

// ---------------------------------------------------------------------------
// Fused differential attention + RMS norm (unchanged from R1 baseline).
// ---------------------------------------------------------------------------
__global__ __launch_bounds__(256) void attn_kernel(const float* __restrict__ rms_w) {
    const int qt = blockIdx.x;       // 0..15
    const int bh = blockIdx.y;       // 0..63
    const int b  = bh >> 4, h = bh & 15;
    const int kh = h >> 1;
    const int tid = threadIdx.x;

    __shared__ float sQ1[64 * 32], sQ2[64 * 32];
    __shared__ float sV[32 * 64];
    __shared__ float sKP[4096];
    __shared__ float sM1[64], sL1[64], sC1[64], sM2[64], sL2[64], sC2[64];

    const int rowBase = b * 1024 + qt * 64;

    for (int i = tid; i < 512; i += 256) {
        int q  = i >> 3;
        int d4 = (i & 7) << 2;
        const float* src = &g_qkv[(rowBase + q) * 2048 + h * 64 + d4];
        float4 v1 = *(const float4*)src;
        float4 v2 = *(const float4*)(src + 32);
        v1.x *= QK_SCALE; v1.y *= QK_SCALE; v1.z *= QK_SCALE; v1.w *= QK_SCALE;
        v2.x *= QK_SCALE; v2.y *= QK_SCALE; v2.z *= QK_SCALE; v2.w *= QK_SCALE;
        *(float4*)&sQ1[q * 32 + d4] = v1;
        *(float4*)&sQ2[q * 32 + d4] = v2;
    }
    if (tid < 64) { sM1[tid] = -1e30f; sL1[tid] = 0.f; sM2[tid] = -1e30f; sL2[tid] = 0.f; }
    __syncthreads();

    const int qg = tid >> 4;
    const int kg = tid & 15;

    float o1[4][4], o2[4][4];
    #pragma unroll
    for (int i = 0; i < 4; i++)
        #pragma unroll
        for (int j = 0; j < 4; j++) { o1[i][j] = 0.f; o2[i][j] = 0.f; }

    const int nch = 2 * qt + 2;
    for (int c = 0; c < nch; ++c) {
        const int kb = c << 5;

        for (int i = tid; i < 1024; i += 256) {
            if (i < 512) {
                int s  = i >> 8;
                int ii = i & 255;
                int j  = ii >> 3, d4 = (ii & 7) << 2;
                float4 v = *(const float4*)&g_qkv[(b * 1024 + kb + j) * 2048 + 1024 + kh * 64 + s * 32 + d4];
                *(float4*)&sKP[s * 1024 + j * 32 + d4] = v;
            } else {
                int ii = i - 512;
                int j  = ii >> 4, d4 = (ii & 15) << 2;
                float4 v = *(const float4*)&g_qkv[(b * 1024 + kb + j) * 2048 + 1536 + kh * 64 + d4];
                *(float4*)&sV[j * 64 + d4] = v;
            }
        }
        __syncthreads();

        float s1[4][2], s2[4][2];
        #pragma unroll
        for (int i = 0; i < 4; i++) { s1[i][0] = s1[i][1] = 0.f; s2[i][0] = s2[i][1] = 0.f; }

        const float4* Q1f = (const float4*)sQ1;
        const float4* Q2f = (const float4*)sQ2;
        const float4* K1f = (const float4*)sKP;
        const float4* K2f = (const float4*)(sKP + 1024);
        #pragma unroll
        for (int dd = 0; dd < 8; ++dd) {
            float4 ka  = K1f[(kg * 2 + 0) * 8 + dd];
            float4 kb4 = K1f[(kg * 2 + 1) * 8 + dd];
            #pragma unroll
            for (int i = 0; i < 4; i++) {
                float4 qv = Q1f[(qg * 4 + i) * 8 + dd];
                s1[i][0] += qv.x * ka.x + qv.y * ka.y + qv.z * ka.z + qv.w * ka.w;
                s1[i][1] += qv.x * kb4.x + qv.y * kb4.y + qv.z * kb4.z + qv.w * kb4.w;
            }
            float4 kc = K2f[(kg * 2 + 0) * 8 + dd];
            float4 kd = K2f[(kg * 2 + 1) * 8 + dd];
            #pragma unroll
            for (int i = 0; i < 4; i++) {
                float4 qv = Q2f[(qg * 4 + i) * 8 + dd];
                s2[i][0] += qv.x * kc.x + qv.y * kc.y + qv.z * kc.z + qv.w * kc.w;
                s2[i][1] += qv.x * kd.x + qv.y * kd.y + qv.z * kd.z + qv.w * kd.w;
            }
        }
        __syncthreads();

        const bool maskCh = (c >= 2 * qt);
        #pragma unroll
        for (int i = 0; i < 4; i++) {
            const int q  = qg * 4 + i;
            const int qa = qt * 64 + q;
            if (maskCh) {
                if (kb + kg * 2 + 0 > qa) { s1[i][0] = -1e30f; s2[i][0] = -1e30f; }
                if (kb + kg * 2 + 1 > qa) { s1[i][1] = -1e30f; s2[i][1] = -1e30f; }
            }
            {
                float mOld = sM1[q];
                float ml = fmaxf(s1[i][0], s1[i][1]);
                #pragma unroll
                for (int o = 8; o; o >>= 1) ml = fmaxf(ml, __shfl_xor_sync(0xffffffffu, ml, o));
                float mNew = fmaxf(mOld, ml);
                float p0 = expf(s1[i][0] - mNew);
                float p1 = expf(s1[i][1] - mNew);
                float ls = p0 + p1;
                #pragma unroll
                for (int o = 8; o; o >>= 1) ls += __shfl_xor_sync(0xffffffffu, ls, o);
                sKP[q * 32 + kg * 2 + 0] = p0;
                sKP[q * 32 + kg * 2 + 1] = p1;
                if (kg == 0) {
                    float cc = expf(mOld - mNew);
                    sC1[q] = cc; sM1[q] = mNew; sL1[q] = sL1[q] * cc + ls;
                }
            }
            {
                float mOld = sM2[q];
                float ml = fmaxf(s2[i][0], s2[i][1]);
                #pragma unroll
                for (int o = 8; o; o >>= 1) ml = fmaxf(ml, __shfl_xor_sync(0xffffffffu, ml, o));
                float mNew = fmaxf(mOld, ml);
                float p0 = expf(s2[i][0] - mNew);
                float p1 = expf(s2[i][1] - mNew);
                float ls = p0 + p1;
                #pragma unroll
                for (int o = 8; o; o >>= 1) ls += __shfl_xor_sync(0xffffffffu, ls, o);
                sKP[2048 + q * 32 + kg * 2 + 0] = p0;
                sKP[2048 + q * 32 + kg * 2 + 1] = p1;
                if (kg == 0) {
                    float cc = expf(mOld - mNew);
                    sC2[q] = cc; sM2[q] = mNew; sL2[q] = sL2[q] * cc + ls;
                }
            }
        }
        __syncthreads();

        #pragma unroll
        for (int i = 0; i < 4; i++) {
            const int q = qg * 4 + i;
            float c1 = sC1[q], c2 = sC2[q];
            #pragma unroll
            for (int j = 0; j < 4; j++) { o1[i][j] *= c1; o2[i][j] *= c2; }
        }
        #pragma unroll 4
        for (int k = 0; k < 32; k++) {
            float4 vv = *(const float4*)&sV[k * 64 + kg * 4];
            #pragma unroll
            for (int i = 0; i < 4; i++) {
                float p1v = sKP[(qg * 4 + i) * 32 + k];
                float p2v = sKP[2048 + (qg * 4 + i) * 32 + k];
                o1[i][0] += p1v * vv.x; o1[i][1] += p1v * vv.y;
                o1[i][2] += p1v * vv.z; o1[i][3] += p1v * vv.w;
                o2[i][0] += p2v * vv.x; o2[i][1] += p2v * vv.y;
                o2[i][2] += p2v * vv.z; o2[i][3] += p2v * vv.w;
            }
        }
        __syncthreads();
    }

    const float lam = g_lambda;
    const float4 wv = *(const float4*)&rms_w[kg * 4];
    #pragma unroll
    for (int i = 0; i < 4; i++) {
        const int q = qg * 4 + i;
        float inv1 = 1.f / sL1[q];
        float inv2 = lam / sL2[q];
        float a0 = o1[i][0] * inv1 - o2[i][0] * inv2;
        float a1 = o1[i][1] * inv1 - o2[i][1] * inv2;
        float a2 = o1[i][2] * inv1 - o2[i][2] * inv2;
        float a3 = o1[i][3] * inv1 - o2[i][3] * inv2;
        float ssq = a0 * a0 + a1 * a1 + a2 * a2 + a3 * a3;
        #pragma unroll
        for (int o = 8; o; o >>= 1) ssq += __shfl_xor_sync(0xffffffffu, ssq, o);
        float invr = rsqrtf(ssq * (1.0f / 64.0f) + 1e-6f) * ONE_MINUS_LI;
        float4 outv = { a0 * invr * wv.x, a1 * invr * wv.y,
                        a2 * invr * wv.z, a3 * invr * wv.w };
        *(float4*)&g_attn[(rowBase + q) * 1024 + h * 64 + kg * 4] = outv;
    }
}

// ---------------------------------------------------------------------------
extern "C" void kernel_launch(void* const* d_in, const int* in_sizes, int n_in,
                              void* d_out, int out_size) {
    (void)in_sizes; (void)n_in; (void)out_size;
    const float* x   = (const float*)d_in[0];
    const float* Wq  = (const float*)d_in[1];
    const float* Wk  = (const float*)d_in[2];
    const float* Wv  = (const float*)d_in[3];
    const float* Wo  = (const float*)d_in[4];
    const float* lq1 = (const float*)d_in[5];
    const float* lk1 = (const float*)d_in[6];
    const float* lq2 = (const float*)d_in[7];
    const float* lk2 = (const float*)d_in[8];
    const float* rw  = (const float*)d_in[9];
    float* out = (float*)d_out;

    lambda_kernel<<<1, 32>>>(lq1, lk1, lq2, lk2);
    gemm_qkv_tc<<<dim3(16, 32), 256>>>(x, Wq, Wk, Wv);
    rope_kernel<<<4096, 256>>>();
    attn_kernel<<<dim3(16, 64), 256>>>(rw);
    gemm_out_tc<<<dim3(8, 32), 256>>>(Wo, out);
}

// round 4
// speedup vs baseline: 1.3795x; 1.0443x over previous
#include <cuda_runtime.h>
#include <math.h>
#include <stdint.h>

// Problem constants: B=4, T=1024, E=1024, H=16, KVH=8, HD=32, N_REP=2
#define LAMBDA_INIT_F 0.7836057665316245f
#define ONE_MINUS_LI  0.2163942334683755f
#define QK_SCALE      0.17677669529663687f   // 1/sqrt(32)

// Scratch (device globals — no allocation allowed)
__device__ float g_qkv[4096 * 2048];   // cols [0,1024)=q(raw), [1024,1536)=k(roped), [1536,2048)=v
__device__ float g_attn[4096 * 1024];  // post diff-attn + RMS, pre-Wo
__device__ float g_lambda;
__device__ float g_cos[1024 * 16];
__device__ float g_sin[1024 * 16];

// ---------------------------------------------------------------------------
__global__ void lambda_kernel(const float* __restrict__ lq1, const float* __restrict__ lk1,
                              const float* __restrict__ lq2, const float* __restrict__ lk2) {
    int l = threadIdx.x;
    float a = lq1[l] * lk1[l];
    float b = lq2[l] * lk2[l];
    #pragma unroll
    for (int o = 16; o; o >>= 1) {
        a += __shfl_xor_sync(0xffffffffu, a, o);
        b += __shfl_xor_sync(0xffffffffu, b, o);
    }
    if (l == 0) g_lambda = expf(a) - expf(b) + LAMBDA_INIT_F;
}

// cos/sin tables: [t=0..1023][p=0..15], angle = t * 10000^{-p/16}
__global__ void rope_tables_kernel() {
    int idx = blockIdx.x * 256 + threadIdx.x;   // 64 blocks x 256 = 16384
    int t = idx >> 4, p = idx & 15;
    double ang = (double)t * pow(10000.0, -(double)p / 16.0);
    double r   = fmod(ang, 6.283185307179586);
    float s, c;
    sincosf((float)r, &s, &c);
    g_cos[idx] = c;
    g_sin[idx] = s;
}

// RoPE in place on k cols [1024,1536): 16 heads x 32 dims, pairs (p, p+16)
__global__ __launch_bounds__(256) void rope_k_kernel() {
    const int row = blockIdx.x;      // 0..4095
    const int t   = row & 1023;
    const int i   = threadIdx.x;     // 256 items = 16 heads * 16 pairs
    const int head = i >> 4;
    const int p    = i & 15;
    float c = g_cos[t * 16 + p];
    float s = g_sin[t * 16 + p];
    float* ptr = &g_qkv[row * 2048 + 1024 + head * 32 + p];
    float x1 = ptr[0], x2 = ptr[16];
    ptr[0]  = x1 * c + x2 * s;
    ptr[16] = x2 * c - x1 * s;
}

// ---------------------------------------------------------------------------
// TF32 tensor-core GEMM: C[128,128] tile, K=1024, BK=32 (unchanged from R2)
// ---------------------------------------------------------------------------
__device__ __forceinline__ float ftf32(float x) {
    uint32_t u;
    asm("cvt.rna.tf32.f32 %0, %1;" : "=r"(u) : "f"(x));
    return __uint_as_float(u);
}

#define MMA_TF32(c, a, b)                                              \
    asm volatile(                                                      \
        "mma.sync.aligned.m16n8k8.row.col.f32.tf32.tf32.f32 "          \
        "{%0,%1,%2,%3}, {%4,%5,%6,%7}, {%8,%9}, {%0,%1,%2,%3};"        \
        : "+f"((c)[0]), "+f"((c)[1]), "+f"((c)[2]), "+f"((c)[3])       \
        : "r"((a)[0]), "r"((a)[1]), "r"((a)[2]), "r"((a)[3]),          \
          "r"((b)[0]), "r"((b)[1]))

#define LDA_S 137
#define LDB_S 136

__device__ __forceinline__ void gemm128_tf32_body(
    float* __restrict__ As, float* __restrict__ Bs,
    const float* __restrict__ A, int lda, int m0,
    const float* __restrict__ B, int ldb, int bcol0,
    float* __restrict__ C, int ldc, int ccol0)
{
    const int t    = threadIdx.x;
    const int lane = t & 31, wid = t >> 5;
    const int wm   = (wid >> 2) * 64;
    const int wn   = (wid & 3) * 32;
    const int g    = lane >> 2, tig = lane & 3;

    float acc[4][4][4];
    #pragma unroll
    for (int mt = 0; mt < 4; mt++)
        #pragma unroll
        for (int nt = 0; nt < 4; nt++)
            #pragma unroll
            for (int i = 0; i < 4; i++) acc[mt][nt][i] = 0.f;

    float4 pa[4], pb[4];
    #pragma unroll
    for (int i = 0; i < 4; i++) {
        int idx = t + (i << 8);
        int ar  = idx >> 3, ak = (idx & 7) << 2;
        pa[i] = *(const float4*)&A[(m0 + ar) * lda + ak];
        int bkr = idx >> 5, bc4 = (idx & 31) << 2;
        pb[i] = *(const float4*)&B[bkr * ldb + bcol0 + bc4];
    }

    for (int k0 = 0; k0 < 1024; k0 += 32) {
        #pragma unroll
        for (int i = 0; i < 4; i++) {
            int idx = t + (i << 8);
            int ar  = idx >> 3, ak = (idx & 7) << 2;
            As[(ak + 0) * LDA_S + ar] = ftf32(pa[i].x);
            As[(ak + 1) * LDA_S + ar] = ftf32(pa[i].y);
            As[(ak + 2) * LDA_S + ar] = ftf32(pa[i].z);
            As[(ak + 3) * LDA_S + ar] = ftf32(pa[i].w);
            int bkr = idx >> 5, bc4 = (idx & 31) << 2;
            float4 w4 = { ftf32(pb[i].x), ftf32(pb[i].y), ftf32(pb[i].z), ftf32(pb[i].w) };
            *(float4*)&Bs[bkr * LDB_S + bc4] = w4;
        }
        __syncthreads();

        if (k0 + 32 < 1024) {
            int kn = k0 + 32;
            #pragma unroll
            for (int i = 0; i < 4; i++) {
                int idx = t + (i << 8);
                int ar  = idx >> 3, ak = (idx & 7) << 2;
                pa[i] = *(const float4*)&A[(m0 + ar) * lda + kn + ak];
                int bkr = idx >> 5, bc4 = (idx & 31) << 2;
                pb[i] = *(const float4*)&B[(kn + bkr) * ldb + bcol0 + bc4];
            }
        }

        #pragma unroll
        for (int kk = 0; kk < 32; kk += 8) {
            uint32_t af[4][4], bf[4][2];
            #pragma unroll
            for (int mt = 0; mt < 4; mt++) {
                int rb = wm + mt * 16 + g;
                const float* a0p = &As[(kk + tig) * LDA_S + rb];
                const float* a1p = &As[(kk + tig + 4) * LDA_S + rb];
                af[mt][0] = __float_as_uint(a0p[0]);
                af[mt][1] = __float_as_uint(a0p[8]);
                af[mt][2] = __float_as_uint(a1p[0]);
                af[mt][3] = __float_as_uint(a1p[8]);
            }
            #pragma unroll
            for (int nt = 0; nt < 4; nt++) {
                int cb = wn + nt * 8 + g;
                bf[nt][0] = __float_as_uint(Bs[(kk + tig) * LDB_S + cb]);
                bf[nt][1] = __float_as_uint(Bs[(kk + tig + 4) * LDB_S + cb]);
            }
            #pragma unroll
            for (int mt = 0; mt < 4; mt++)
                #pragma unroll
                for (int nt = 0; nt < 4; nt++)
                    MMA_TF32(acc[mt][nt], af[mt], bf[nt]);
        }
        __syncthreads();
    }

    #pragma unroll
    for (int mt = 0; mt < 4; mt++) {
        #pragma unroll
        for (int nt = 0; nt < 4; nt++) {
            int r  = m0 + wm + mt * 16 + g;
            int cg = ccol0 + wn + nt * 8 + (tig << 1);
            float2 v0 = { acc[mt][nt][0], acc[mt][nt][1] };
            float2 v1 = { acc[mt][nt][2], acc[mt][nt][3] };
            *(float2*)&C[r * ldc + cg]       = v0;
            *(float2*)&C[(r + 8) * ldc + cg] = v1;
        }
    }
}

__global__ __launch_bounds__(256) void gemm_qkv_tc(const float* __restrict__ X,
                                                   const float* __restrict__ Wq,
                                                   const float* __restrict__ Wk,
                                                   const float* __restrict__ Wv) {
    __shared__ float As[32 * LDA_S];
    __shared__ float Bs[32 * LDB_S];
    const int m0 = blockIdx.y * 128;
    const int nt = blockIdx.x;
    const float* Bsel; int ldb, bcol0, ccol0;
    if (nt < 8)       { Bsel = Wq; ldb = 1024; bcol0 = nt * 128;        ccol0 = nt * 128; }
    else if (nt < 12) { Bsel = Wk; ldb = 512;  bcol0 = (nt - 8) * 128;  ccol0 = 1024 + (nt - 8) * 128; }
    else              { Bsel = Wv; ldb = 512;  bcol0 = (nt - 12) * 128; ccol0 = 1536 + (nt - 12) * 128; }
    gemm128_tf32_body(As, Bs, X, 1024, m0, Bsel, ldb, bcol0, g_qkv, 2048, ccol0);
}

__global__ __launch_bounds__(256) void gemm_out_tc(const float* __restrict__ Wo,
                                                   float* __restrict__ out) {
    __shared__ float As[32 * LDA_S];
    __shared__ float Bs[32 * LDB_S];
    const int m0 = blockIdx.y * 128;
    const int n0 = blockIdx.x * 128;
    gemm128_tf32_body(As, Bs, g_attn, 1024, m0, Wo, 1024, n0, out, 1024, n0);
}

// ---------------------------------------------------------------------------
// Fused differential attention + RMS norm.
// Q-RoPE fused into the Q-tile load; P loads in PV are float4; __expf softmax;
// heavy-first qt ordering.
// ---------------------------------------------------------------------------
__global__ __launch_bounds__(256) void attn_kernel(const float* __restrict__ rms_w) {
    const int qt = 15 - blockIdx.x;  // heavy blocks (more chunks) first
    const int bh = blockIdx.y;       // 0..63
    const int b  = bh >> 4, h = bh & 15;
    const int kh = h >> 1;
    const int tid = threadIdx.x;

    __shared__ float sQ1[64 * 32], sQ2[64 * 32];
    __shared__ float sV[32 * 64];
    __shared__ float sKP[4096];      // K1|K2 during scores; P1|P2 after
    __shared__ float sM1[64], sL1[64], sC1[64], sM2[64], sL2[64], sC2[64];

    const int rowBase = b * 1024 + qt * 64;

    // Load Q tiles with fused RoPE + QK scale.
    // 256 items: q (64) x dim-group d4 in {0,4,8,12}; each handles (d4, d4+16) pair.
    {
        const int q  = tid >> 2;
        const int d4 = (tid & 3) << 2;
        const int t  = qt * 64 + q;
        const float* src = &g_qkv[(rowBase + q) * 2048 + h * 64];
        float4 a1 = *(const float4*)&src[d4];
        float4 b1 = *(const float4*)&src[d4 + 16];
        float4 a2 = *(const float4*)&src[32 + d4];
        float4 b2 = *(const float4*)&src[32 + d4 + 16];
        float c0 = g_cos[t * 16 + d4 + 0], s0 = g_sin[t * 16 + d4 + 0];
        float c1 = g_cos[t * 16 + d4 + 1], s1 = g_sin[t * 16 + d4 + 1];
        float c2 = g_cos[t * 16 + d4 + 2], s2 = g_sin[t * 16 + d4 + 2];
        float c3 = g_cos[t * 16 + d4 + 3], s3 = g_sin[t * 16 + d4 + 3];
        float4 r1a = { (a1.x * c0 + b1.x * s0) * QK_SCALE, (a1.y * c1 + b1.y * s1) * QK_SCALE,
                       (a1.z * c2 + b1.z * s2) * QK_SCALE, (a1.w * c3 + b1.w * s3) * QK_SCALE };
        float4 r1b = { (b1.x * c0 - a1.x * s0) * QK_SCALE, (b1.y * c1 - a1.y * s1) * QK_SCALE,
                       (b1.z * c2 - a1.z * s2) * QK_SCALE, (b1.w * c3 - a1.w * s3) * QK_SCALE };
        float4 r2a = { (a2.x * c0 + b2.x * s0) * QK_SCALE, (a2.y * c1 + b2.y * s1) * QK_SCALE,
                       (a2.z * c2 + b2.z * s2) * QK_SCALE, (a2.w * c3 + b2.w * s3) * QK_SCALE };
        float4 r2b = { (b2.x * c0 - a2.x * s0) * QK_SCALE, (b2.y * c1 - a2.y * s1) * QK_SCALE,
                       (b2.z * c2 - a2.z * s2) * QK_SCALE, (b2.w * c3 - a2.w * s3) * QK_SCALE };
        *(float4*)&sQ1[q * 32 + d4]      = r1a;
        *(float4*)&sQ1[q * 32 + d4 + 16] = r1b;
        *(float4*)&sQ2[q * 32 + d4]      = r2a;
        *(float4*)&sQ2[q * 32 + d4 + 16] = r2b;
    }
    if (tid < 64) { sM1[tid] = -1e30f; sL1[tid] = 0.f; sM2[tid] = -1e30f; sL2[tid] = 0.f; }
    __syncthreads();

    const int qg = tid >> 4;
    const int kg = tid & 15;

    float o1[4][4], o2[4][4];
    #pragma unroll
    for (int i = 0; i < 4; i++)
        #pragma unroll
        for (int j = 0; j < 4; j++) { o1[i][j] = 0.f; o2[i][j] = 0.f; }

    const int nch = 2 * qt + 2;
    for (int c = 0; c < nch; ++c) {
        const int kb = c << 5;

        for (int i = tid; i < 1024; i += 256) {
            if (i < 512) {
                int s  = i >> 8;
                int ii = i & 255;
                int j  = ii >> 3, d4 = (ii & 7) << 2;
                float4 v = *(const float4*)&g_qkv[(b * 1024 + kb + j) * 2048 + 1024 + kh * 64 + s * 32 + d4];
                *(float4*)&sKP[s * 1024 + j * 32 + d4] = v;
            } else {
                int ii = i - 512;
                int j  = ii >> 4, d4 = (ii & 15) << 2;
                float4 v = *(const float4*)&g_qkv[(b * 1024 + kb + j) * 2048 + 1536 + kh * 64 + d4];
                *(float4*)&sV[j * 64 + d4] = v;
            }
        }
        __syncthreads();

        // Scores: 4q x 2k per thread, both streams
        float s1[4][2], s2[4][2];
        #pragma unroll
        for (int i = 0; i < 4; i++) { s1[i][0] = s1[i][1] = 0.f; s2[i][0] = s2[i][1] = 0.f; }

        const float4* Q1f = (const float4*)sQ1;
        const float4* Q2f = (const float4*)sQ2;
        const float4* K1f = (const float4*)sKP;
        const float4* K2f = (const float4*)(sKP + 1024);
        #pragma unroll
        for (int dd = 0; dd < 8; ++dd) {
            float4 ka  = K1f[(kg * 2 + 0) * 8 + dd];
            float4 kb4 = K1f[(kg * 2 + 1) * 8 + dd];
            #pragma unroll
            for (int i = 0; i < 4; i++) {
                float4 qv = Q1f[(qg * 4 + i) * 8 + dd];
                s1[i][0] += qv.x * ka.x + qv.y * ka.y + qv.z * ka.z + qv.w * ka.w;
                s1[i][1] += qv.x * kb4.x + qv.y * kb4.y + qv.z * kb4.z + qv.w * kb4.w;
            }
            float4 kc = K2f[(kg * 2 + 0) * 8 + dd];
            float4 kd = K2f[(kg * 2 + 1) * 8 + dd];
            #pragma unroll
            for (int i = 0; i < 4; i++) {
                float4 qv = Q2f[(qg * 4 + i) * 8 + dd];
                s2[i][0] += qv.x * kc.x + qv.y * kc.y + qv.z * kc.z + qv.w * kc.w;
                s2[i][1] += qv.x * kd.x + qv.y * kd.y + qv.z * kd.z + qv.w * kd.w;
            }
        }
        __syncthreads();    // K reads complete before P overwrites sKP

        const bool maskCh = (c >= 2 * qt);
        #pragma unroll
        for (int i = 0; i < 4; i++) {
            const int q  = qg * 4 + i;
            const int qa = qt * 64 + q;
            if (maskCh) {
                if (kb + kg * 2 + 0 > qa) { s1[i][0] = -1e30f; s2[i][0] = -1e30f; }
                if (kb + kg * 2 + 1 > qa) { s1[i][1] = -1e30f; s2[i][1] = -1e30f; }
            }
            {
                float mOld = sM1[q];
                float ml = fmaxf(s1[i][0], s1[i][1]);
                #pragma unroll
                for (int o = 8; o; o >>= 1) ml = fmaxf(ml, __shfl_xor_sync(0xffffffffu, ml, o));
                float mNew = fmaxf(mOld, ml);
                float p0 = __expf(s1[i][0] - mNew);
                float p1 = __expf(s1[i][1] - mNew);
                float ls = p0 + p1;
                #pragma unroll
                for (int o = 8; o; o >>= 1) ls += __shfl_xor_sync(0xffffffffu, ls, o);
                sKP[q * 32 + kg * 2 + 0] = p0;
                sKP[q * 32 + kg * 2 + 1] = p1;
                if (kg == 0) {
                    float cc = __expf(mOld - mNew);
                    sC1[q] = cc; sM1[q] = mNew; sL1[q] = sL1[q] * cc + ls;
                }
            }
            {
                float mOld = sM2[q];
                float ml = fmaxf(s2[i][0], s2[i][1]);
                #pragma unroll
                for (int o = 8; o; o >>= 1) ml = fmaxf(ml, __shfl_xor_sync(0xffffffffu, ml, o));
                float mNew = fmaxf(mOld, ml);
                float p0 = __expf(s2[i][0] - mNew);
                float p1 = __expf(s2[i][1] - mNew);
                float ls = p0 + p1;
                #pragma unroll
                for (int o = 8; o; o >>= 1) ls += __shfl_xor_sync(0xffffffffu, ls, o);
                sKP[2048 + q * 32 + kg * 2 + 0] = p0;
                sKP[2048 + q * 32 + kg * 2 + 1] = p1;
                if (kg == 0) {
                    float cc = __expf(mOld - mNew);
                    sC2[q] = cc; sM2[q] = mNew; sL2[q] = sL2[q] * cc + ls;
                }
            }
        }
        __syncthreads();

        // PV: rescale accumulators, then O += P * V.  P loads are float4 now.
        #pragma unroll
        for (int i = 0; i < 4; i++) {
            const int q = qg * 4 + i;
            float c1 = sC1[q], c2 = sC2[q];
            #pragma unroll
            for (int j = 0; j < 4; j++) { o1[i][j] *= c1; o2[i][j] *= c2; }
        }
        #pragma unroll 2
        for (int k4 = 0; k4 < 32; k4 += 4) {
            float4 vv0 = *(const float4*)&sV[(k4 + 0) * 64 + kg * 4];
            float4 vv1 = *(const float4*)&sV[(k4 + 1) * 64 + kg * 4];
            float4 vv2 = *(const float4*)&sV[(k4 + 2) * 64 + kg * 4];
            float4 vv3 = *(const float4*)&sV[(k4 + 3) * 64 + kg * 4];
            #pragma unroll
            for (int i = 0; i < 4; i++) {
                float4 p1 = *(const float4*)&sKP[(qg * 4 + i) * 32 + k4];
                float4 p2 = *(const float4*)&sKP[2048 + (qg * 4 + i) * 32 + k4];
                o1[i][0] += p1.x * vv0.x + p1.y * vv1.x + p1.z * vv2.x + p1.w * vv3.x;
                o1[i][1] += p1.x * vv0.y + p1.y * vv1.y + p1.z * vv2.y + p1.w * vv3.y;
                o1[i][2] += p1.x * vv0.z + p1.y * vv1.z + p1.z * vv2.z + p1.w * vv3.z;
                o1[i][3] += p1.x * vv0.w + p1.y * vv1.w + p1.z * vv2.w + p1.w * vv3.w;
                o2[i][0] += p2.x * vv0.x + p2.y * vv1.x + p2.z * vv2.x + p2.w * vv3.x;
                o2[i][1] += p2.x * vv0.y + p2.y * vv1.y + p2.z * vv2.y + p2.w * vv3.y;
                o2[i][2] += p2.x * vv0.z + p2.y * vv1.z + p2.z * vv2.z + p2.w * vv3.z;
                o2[i][3] += p2.x * vv0.w + p2.y * vv1.w + p2.z * vv2.w + p2.w * vv3.w;
            }
        }
        __syncthreads();
    }

    // Epilogue: diff, RMS norm over 64 dims, weight, scale; write g_attn
    const float lam = g_lambda;
    const float4 wv = *(const float4*)&rms_w[kg * 4];
    #pragma unroll
    for (int i = 0; i < 4; i++) {
        const int q = qg * 4 + i;
        float inv1 = 1.f / sL1[q];
        float inv2 = lam / sL2[q];
        float a0 = o1[i][0] * inv1 - o2[i][0] * inv2;
        float a1 = o1[i][1] * inv1 - o2[i][1] * inv2;
        float a2 = o1[i][2] * inv1 - o2[i][2] * inv2;
        float a3 = o1[i][3] * inv1 - o2[i][3] * inv2;
        float ssq = a0 * a0 + a1 * a1 + a2 * a2 + a3 * a3;
        #pragma unroll
        for (int o = 8; o; o >>= 1) ssq += __shfl_xor_sync(0xffffffffu, ssq, o);
        float invr = rsqrtf(ssq * (1.0f / 64.0f) + 1e-6f) * ONE_MINUS_LI;
        float4 outv = { a0 * invr * wv.x, a1 * invr * wv.y,
                        a2 * invr * wv.z, a3 * invr * wv.w };
        *(float4*)&g_attn[(rowBase + q) * 1024 + h * 64 + kg * 4] = outv;
    }
}

// ---------------------------------------------------------------------------
extern "C" void kernel_launch(void* const* d_in, const int* in_sizes, int n_in,
                              void* d_out, int out_size) {
    (void)in_sizes; (void)n_in; (void)out_size;
    const float* x   = (const float*)d_in[0];
    const float* Wq  = (const float*)d_in[1];
    const float* Wk  = (const float*)d_in[2];
    const float* Wv  = (const float*)d_in[3];
    const float* Wo  = (const float*)d_in[4];
    const float* lq1 = (const float*)d_in[5];
    const float* lk1 = (const float*)d_in[6];
    const float* lq2 = (const float*)d_in[7];
    const float* lk2 = (const float*)d_in[8];
    const float* rw  = (const float*)d_in[9];
    float* out = (float*)d_out;

    lambda_kernel<<<1, 32>>>(lq1, lk1, lq2, lk2);
    rope_tables_kernel<<<64, 256>>>();
    gemm_qkv_tc<<<dim3(16, 32), 256>>>(x, Wq, Wk, Wv);
    rope_k_kernel<<<4096, 256>>>();
    attn_kernel<<<dim3(16, 64), 256>>>(rw);
    gemm_out_tc<<<dim3(8, 32), 256>>>(Wo, out);
}

// round 8
// speedup vs baseline: 2.3539x; 1.7063x over previous
#include <cuda_runtime.h>
#include <cuda_fp16.h>
#include <math.h>
#include <stdint.h>

// Problem constants: B=4, T=1024, E=1024, H=16, KVH=8, HD=32, N_REP=2
#define LAMBDA_INIT_F 0.7836057665316245f
#define ONE_MINUS_LI  0.2163942334683755f
#define QK_SCALE      0.17677669529663687f   // 1/sqrt(32)

// Scratch (device globals — no allocation allowed)
__device__ float g_qkv[4096 * 2048];   // cols [0,1024)=q(raw), [1024,1536)=k(roped), [1536,2048)=v
__device__ float g_attn[4096 * 1024];  // post diff-attn + RMS, pre-Wo
__device__ float g_lambda;
__device__ float g_cos[1024 * 16];
__device__ float g_sin[1024 * 16];

// ---------------------------------------------------------------------------
__global__ void lambda_kernel(const float* __restrict__ lq1, const float* __restrict__ lk1,
                              const float* __restrict__ lq2, const float* __restrict__ lk2) {
    int l = threadIdx.x;
    float a = lq1[l] * lk1[l];
    float b = lq2[l] * lk2[l];
    #pragma unroll
    for (int o = 16; o; o >>= 1) {
        a += __shfl_xor_sync(0xffffffffu, a, o);
        b += __shfl_xor_sync(0xffffffffu, b, o);
    }
    if (l == 0) g_lambda = expf(a) - expf(b) + LAMBDA_INIT_F;
}

// cos/sin tables: [t=0..1023][p=0..15], angle = t * 10000^{-p/16}
__global__ void rope_tables_kernel() {
    int idx = blockIdx.x * 256 + threadIdx.x;   // 64 blocks x 256 = 16384
    int t = idx >> 4, p = idx & 15;
    double ang = (double)t * pow(10000.0, -(double)p / 16.0);
    double r   = fmod(ang, 6.283185307179586);
    float s, c;
    sincosf((float)r, &s, &c);
    g_cos[idx] = c;
    g_sin[idx] = s;
}

// RoPE in place on k cols [1024,1536): 16 heads x 32 dims, pairs (p, p+16)
__global__ __launch_bounds__(256) void rope_k_kernel() {
    const int row = blockIdx.x;      // 0..4095
    const int t   = row & 1023;
    const int i   = threadIdx.x;     // 256 items = 16 heads * 16 pairs
    const int head = i >> 4;
    const int p    = i & 15;
    float c = g_cos[t * 16 + p];
    float s = g_sin[t * 16 + p];
    float* ptr = &g_qkv[row * 2048 + 1024 + head * 32 + p];
    float x1 = ptr[0], x2 = ptr[16];
    ptr[0]  = x1 * c + x2 * s;
    ptr[16] = x2 * c - x1 * s;
}

// ---------------------------------------------------------------------------
// TF32 tensor-core GEMM: C[128,128] tile, K=1024, BK=32 (unchanged)
// ---------------------------------------------------------------------------
__device__ __forceinline__ float ftf32(float x) {
    uint32_t u;
    asm("cvt.rna.tf32.f32 %0, %1;" : "=r"(u) : "f"(x));
    return __uint_as_float(u);
}

#define MMA_TF32(c, a, b)                                              \
    asm volatile(                                                      \
        "mma.sync.aligned.m16n8k8.row.col.f32.tf32.tf32.f32 "          \
        "{%0,%1,%2,%3}, {%4,%5,%6,%7}, {%8,%9}, {%0,%1,%2,%3};"        \
        : "+f"((c)[0]), "+f"((c)[1]), "+f"((c)[2]), "+f"((c)[3])       \
        : "r"((a)[0]), "r"((a)[1]), "r"((a)[2]), "r"((a)[3]),          \
          "r"((b)[0]), "r"((b)[1]))

#define LDA_S 137
#define LDB_S 136

__device__ __forceinline__ void gemm128_tf32_body(
    float* __restrict__ As, float* __restrict__ Bs,
    const float* __restrict__ A, int lda, int m0,
    const float* __restrict__ B, int ldb, int bcol0,
    float* __restrict__ C, int ldc, int ccol0)
{
    const int t    = threadIdx.x;
    const int lane = t & 31, wid = t >> 5;
    const int wm   = (wid >> 2) * 64;
    const int wn   = (wid & 3) * 32;
    const int g    = lane >> 2, tig = lane & 3;

    float acc[4][4][4];
    #pragma unroll
    for (int mt = 0; mt < 4; mt++)
        #pragma unroll
        for (int nt = 0; nt < 4; nt++)
            #pragma unroll
            for (int i = 0; i < 4; i++) acc[mt][nt][i] = 0.f;

    float4 pa[4], pb[4];
    #pragma unroll
    for (int i = 0; i < 4; i++) {
        int idx = t + (i << 8);
        int ar  = idx >> 3, ak = (idx & 7) << 2;
        pa[i] = *(const float4*)&A[(m0 + ar) * lda + ak];
        int bkr = idx >> 5, bc4 = (idx & 31) << 2;
        pb[i] = *(const float4*)&B[bkr * ldb + bcol0 + bc4];
    }

    for (int k0 = 0; k0 < 1024; k0 += 32) {
        #pragma unroll
        for (int i = 0; i < 4; i++) {
            int idx = t + (i << 8);
            int ar  = idx >> 3, ak = (idx & 7) << 2;
            As[(ak + 0) * LDA_S + ar] = ftf32(pa[i].x);
            As[(ak + 1) * LDA_S + ar] = ftf32(pa[i].y);
            As[(ak + 2) * LDA_S + ar] = ftf32(pa[i].z);
            As[(ak + 3) * LDA_S + ar] = ftf32(pa[i].w);
            int bkr = idx >> 5, bc4 = (idx & 31) << 2;
            float4 w4 = { ftf32(pb[i].x), ftf32(pb[i].y), ftf32(pb[i].z), ftf32(pb[i].w) };
            *(float4*)&Bs[bkr * LDB_S + bc4] = w4;
        }
        __syncthreads();

        if (k0 + 32 < 1024) {
            int kn = k0 + 32;
            #pragma unroll
            for (int i = 0; i < 4; i++) {
                int idx = t + (i << 8);
                int ar  = idx >> 3, ak = (idx & 7) << 2;
                pa[i] = *(const float4*)&A[(m0 + ar) * lda + kn + ak];
                int bkr = idx >> 5, bc4 = (idx & 31) << 2;
                pb[i] = *(const float4*)&B[(kn + bkr) * ldb + bcol0 + bc4];
            }
        }

        #pragma unroll
        for (int kk = 0; kk < 32; kk += 8) {
            uint32_t af[4][4], bf[4][2];
            #pragma unroll
            for (int mt = 0; mt < 4; mt++) {
                int rb = wm + mt * 16 + g;
                const float* a0p = &As[(kk + tig) * LDA_S + rb];
                const float* a1p = &As[(kk + tig + 4) * LDA_S + rb];
                af[mt][0] = __float_as_uint(a0p[0]);
                af[mt][1] = __float_as_uint(a0p[8]);
                af[mt][2] = __float_as_uint(a1p[0]);
                af[mt][3] = __float_as_uint(a1p[8]);
            }
            #pragma unroll
            for (int nt = 0; nt < 4; nt++) {
                int cb = wn + nt * 8 + g;
                bf[nt][0] = __float_as_uint(Bs[(kk + tig) * LDB_S + cb]);
                bf[nt][1] = __float_as_uint(Bs[(kk + tig + 4) * LDB_S + cb]);
            }
            #pragma unroll
            for (int mt = 0; mt < 4; mt++)
                #pragma unroll
                for (int nt = 0; nt < 4; nt++)
                    MMA_TF32(acc[mt][nt], af[mt], bf[nt]);
        }
        __syncthreads();
    }

    #pragma unroll
    for (int mt = 0; mt < 4; mt++) {
        #pragma unroll
        for (int nt = 0; nt < 4; nt++) {
            int r  = m0 + wm + mt * 16 + g;
            int cg = ccol0 + wn + nt * 8 + (tig << 1);
            float2 v0 = { acc[mt][nt][0], acc[mt][nt][1] };
            float2 v1 = { acc[mt][nt][2], acc[mt][nt][3] };
            *(float2*)&C[r * ldc + cg]       = v0;
            *(float2*)&C[(r + 8) * ldc + cg] = v1;
        }
    }
}

__global__ __launch_bounds__(256) void gemm_qkv_tc(const float* __restrict__ X,
                                                   const float* __restrict__ Wq,
                                                   const float* __restrict__ Wk,
                                                   const float* __restrict__ Wv) {
    __shared__ float As[32 * LDA_S];
    __shared__ float Bs[32 * LDB_S];
    const int m0 = blockIdx.y * 128;
    const int nt = blockIdx.x;
    const float* Bsel; int ldb, bcol0, ccol0;
    if (nt < 8)       { Bsel = Wq; ldb = 1024; bcol0 = nt * 128;        ccol0 = nt * 128; }
    else if (nt < 12) { Bsel = Wk; ldb = 512;  bcol0 = (nt - 8) * 128;  ccol0 = 1024 + (nt - 8) * 128; }
    else              { Bsel = Wv; ldb = 512;  bcol0 = (nt - 12) * 128; ccol0 = 1536 + (nt - 12) * 128; }
    gemm128_tf32_body(As, Bs, X, 1024, m0, Bsel, ldb, bcol0, g_qkv, 2048, ccol0);
}

__global__ __launch_bounds__(256) void gemm_out_tc(const float* __restrict__ Wo,
                                                   float* __restrict__ out) {
    __shared__ float As[32 * LDA_S];
    __shared__ float Bs[32 * LDB_S];
    const int m0 = blockIdx.y * 128;
    const int n0 = blockIdx.x * 128;
    gemm128_tf32_body(As, Bs, g_attn, 1024, m0, Wo, 1024, n0, out, 1024, n0);
}

// ---------------------------------------------------------------------------
// cp.async helpers
// ---------------------------------------------------------------------------
__device__ __forceinline__ void cp_async16(void* smem_dst, const void* gmem_src) {
    uint32_t s = (uint32_t)__cvta_generic_to_shared(smem_dst);
    asm volatile("cp.async.cg.shared.global [%0], [%1], 16;\n" :: "r"(s), "l"(gmem_src));
}
__device__ __forceinline__ void cp_commit()  { asm volatile("cp.async.commit_group;\n"); }
__device__ __forceinline__ void cp_wait0()   { asm volatile("cp.async.wait_group 0;\n"); }
__device__ __forceinline__ void cp_wait1()   { asm volatile("cp.async.wait_group 1;\n"); }

// ---------------------------------------------------------------------------
// Fused differential attention + RMS norm.
//  - K padded to row stride 36 floats, keys per thread = (kg, kg+16): 2-way max conflicts
//  - cp.async: K double-buffered one chunk ahead; V prefetched at chunk top
//  - P stored as fp16 aliasing the consumed K region of the current stage
//  - softmax stats (M,L) in registers on kg==0 lane, broadcast by shuffle
// ---------------------------------------------------------------------------
#define KSTRIDE 36
#define K2OFF   1152    // 32*36

__global__ __launch_bounds__(256) void attn_kernel(const float* __restrict__ rms_w) {
    const int qt = 15 - blockIdx.x;  // heavy blocks first
    const int bh = blockIdx.y;       // 0..63
    const int b  = bh >> 4, h = bh & 15;
    const int kh = h >> 1;
    const int tid = threadIdx.x;

    __shared__ float sQ1[2048], sQ2[2048];  // 64x32 each
    __shared__ float sK[2][2304];           // per stage: K1 rows*36 | K2 at +1152 ; P aliases after use
    __shared__ float sVb[2048];             // 32x64, single buffer

    const int rowBase = b * 1024 + qt * 64;
    const int nch = 2 * qt + 2;

    // ---- prefetch K chunk 0 into stage 0 ----
    {
        const int kb = 0;
        #pragma unroll
        for (int kk = 0; kk < 2; kk++) {
            int i = tid + (kk << 8);          // 0..511 : K halves (16B units)
            int j = i >> 4, c16 = i & 15;
            const float* src = &g_qkv[(size_t)(b * 1024 + kb + j) * 2048 + 1024 + kh * 64 + c16 * 4];
            float* dst = (c16 < 8) ? &sK[0][j * KSTRIDE + c16 * 4]
                                   : &sK[0][K2OFF + j * KSTRIDE + (c16 - 8) * 4];
            cp_async16(dst, src);
        }
        cp_commit();
    }

    // ---- load Q tiles with fused RoPE + QK scale ----
    {
        const int q  = tid >> 2;
        const int d4 = (tid & 3) << 2;
        const int t  = qt * 64 + q;
        const float* src = &g_qkv[(size_t)(rowBase + q) * 2048 + h * 64];
        float4 a1 = *(const float4*)&src[d4];
        float4 b1 = *(const float4*)&src[d4 + 16];
        float4 a2 = *(const float4*)&src[32 + d4];
        float4 b2 = *(const float4*)&src[32 + d4 + 16];
        float c0 = g_cos[t * 16 + d4 + 0], s0 = g_sin[t * 16 + d4 + 0];
        float c1 = g_cos[t * 16 + d4 + 1], s1 = g_sin[t * 16 + d4 + 1];
        float c2 = g_cos[t * 16 + d4 + 2], s2 = g_sin[t * 16 + d4 + 2];
        float c3 = g_cos[t * 16 + d4 + 3], s3 = g_sin[t * 16 + d4 + 3];
        float4 r1a = { (a1.x * c0 + b1.x * s0) * QK_SCALE, (a1.y * c1 + b1.y * s1) * QK_SCALE,
                       (a1.z * c2 + b1.z * s2) * QK_SCALE, (a1.w * c3 + b1.w * s3) * QK_SCALE };
        float4 r1b = { (b1.x * c0 - a1.x * s0) * QK_SCALE, (b1.y * c1 - a1.y * s1) * QK_SCALE,
                       (b1.z * c2 - a1.z * s2) * QK_SCALE, (b1.w * c3 - a1.w * s3) * QK_SCALE };
        float4 r2a = { (a2.x * c0 + b2.x * s0) * QK_SCALE, (a2.y * c1 + b2.y * s1) * QK_SCALE,
                       (a2.z * c2 + b2.z * s2) * QK_SCALE, (a2.w * c3 + b2.w * s3) * QK_SCALE };
        float4 r2b = { (b2.x * c0 - a2.x * s0) * QK_SCALE, (b2.y * c1 - a2.y * s1) * QK_SCALE,
                       (b2.z * c2 - a2.z * s2) * QK_SCALE, (b2.w * c3 - a2.w * s3) * QK_SCALE };
        *(float4*)&sQ1[q * 32 + d4]      = r1a;
        *(float4*)&sQ1[q * 32 + d4 + 16] = r1b;
        *(float4*)&sQ2[q * 32 + d4]      = r2a;
        *(float4*)&sQ2[q * 32 + d4 + 16] = r2b;
    }

    const int qg  = tid >> 4;      // row group: rows qg*4+i
    const int kg  = tid & 15;      // keys kg and kg+16 ; PV dims kg*4+j
    const int lane = tid & 31;
    const int src0 = lane & 16;    // kg==0 lane of this row group
    const unsigned FULL = 0xffffffffu;

    float o1[4][4], o2[4][4];
    float rM1[4], rL1[4], rM2[4], rL2[4];
    #pragma unroll
    for (int i = 0; i < 4; i++) {
        rM1[i] = -1e30f; rL1[i] = 0.f; rM2[i] = -1e30f; rL2[i] = 0.f;
        #pragma unroll
        for (int j = 0; j < 4; j++) { o1[i][j] = 0.f; o2[i][j] = 0.f; }
    }

    for (int c = 0; c < nch; ++c) {
        const int s = c & 1;
        cp_wait0();                 // K(c) ready (only pending group at this point)
        __syncthreads();            // all threads past prev PV; K(c) visible

        // prefetch V(c) (single buffer; consumed later this chunk)
        {
            const int kb = c << 5;
            #pragma unroll
            for (int kk = 0; kk < 2; kk++) {
                int i = tid + (kk << 8);
                int j = i >> 4, c16 = i & 15;
                const float* src = &g_qkv[(size_t)(b * 1024 + kb + j) * 2048 + 1536 + kh * 64 + c16 * 4];
                cp_async16(&sVb[j * 64 + c16 * 4], src);
            }
            cp_commit();
        }
        // prefetch K(c+1) into other stage
        if (c + 1 < nch) {
            const int kb = (c + 1) << 5;
            #pragma unroll
            for (int kk = 0; kk < 2; kk++) {
                int i = tid + (kk << 8);
                int j = i >> 4, c16 = i & 15;
                const float* src = &g_qkv[(size_t)(b * 1024 + kb + j) * 2048 + 1024 + kh * 64 + c16 * 4];
                float* dst = (c16 < 8) ? &sK[s ^ 1][j * KSTRIDE + c16 * 4]
                                       : &sK[s ^ 1][K2OFF + j * KSTRIDE + (c16 - 8) * 4];
                cp_async16(dst, src);
            }
            cp_commit();
        }

        // ---- scores: 4 rows x 2 keys (kg, kg+16), both streams ----
        float s1[4][2], s2[4][2];
        #pragma unroll
        for (int i = 0; i < 4; i++) { s1[i][0] = s1[i][1] = 0.f; s2[i][0] = s2[i][1] = 0.f; }

        const float4* Q1f = (const float4*)sQ1;
        const float4* Q2f = (const float4*)sQ2;
        const float4* K1a = (const float4*)&sK[s][kg * KSTRIDE];
        const float4* K1b = (const float4*)&sK[s][(kg + 16) * KSTRIDE];
        const float4* K2a = (const float4*)&sK[s][K2OFF + kg * KSTRIDE];
        const float4* K2b = (const float4*)&sK[s][K2OFF + (kg + 16) * KSTRIDE];
        #pragma unroll
        for (int dd = 0; dd < 8; ++dd) {
            float4 ka  = K1a[dd];
            float4 kb4 = K1b[dd];
            #pragma unroll
            for (int i = 0; i < 4; i++) {
                float4 qv = Q1f[(qg * 4 + i) * 8 + dd];
                s1[i][0] += qv.x * ka.x + qv.y * ka.y + qv.z * ka.z + qv.w * ka.w;
                s1[i][1] += qv.x * kb4.x + qv.y * kb4.y + qv.z * kb4.z + qv.w * kb4.w;
            }
            float4 kc = K2a[dd];
            float4 kd = K2b[dd];
            #pragma unroll
            for (int i = 0; i < 4; i++) {
                float4 qv = Q2f[(qg * 4 + i) * 8 + dd];
                s2[i][0] += qv.x * kc.x + qv.y * kc.y + qv.z * kc.z + qv.w * kc.w;
                s2[i][1] += qv.x * kd.x + qv.y * kd.y + qv.z * kd.z + qv.w * kd.w;
            }
        }
        __syncthreads();    // all K(s) reads done before P overwrites the region

        __half* hP1 = (__half*)&sK[s][0];     // P1: 64x32 half = 4KB
        __half* hP2 = hP1 + 2048;             // P2: next 4KB (region is 9216B)

        const bool maskCh = (c >= 2 * qt);
        const int kb = c << 5;
        float cc1[4], cc2[4];
        #pragma unroll
        for (int i = 0; i < 4; i++) {
            const int q  = qg * 4 + i;
            const int qa = qt * 64 + q;
            if (maskCh) {
                if (kb + kg > qa)      { s1[i][0] = -1e30f; s2[i][0] = -1e30f; }
                if (kb + kg + 16 > qa) { s1[i][1] = -1e30f; s2[i][1] = -1e30f; }
            }
            // stream 1
            {
                float mOld = __shfl_sync(FULL, rM1[i], src0);
                float ml = fmaxf(s1[i][0], s1[i][1]);
                #pragma unroll
                for (int o = 8; o; o >>= 1) ml = fmaxf(ml, __shfl_xor_sync(FULL, ml, o));
                float mNew = fmaxf(mOld, ml);
                float p0 = __expf(s1[i][0] - mNew);
                float p1 = __expf(s1[i][1] - mNew);
                float ls = p0 + p1;
                #pragma unroll
                for (int o = 8; o; o >>= 1) ls += __shfl_xor_sync(FULL, ls, o);
                cc1[i] = __expf(mOld - mNew);
                if (kg == 0) { rL1[i] = rL1[i] * cc1[i] + ls; rM1[i] = mNew; }
                hP1[q * 32 + kg]      = __float2half_rn(p0);
                hP1[q * 32 + kg + 16] = __float2half_rn(p1);
            }
            // stream 2
            {
                float mOld = __shfl_sync(FULL, rM2[i], src0);
                float ml = fmaxf(s2[i][0], s2[i][1]);
                #pragma unroll
                for (int o = 8; o; o >>= 1) ml = fmaxf(ml, __shfl_xor_sync(FULL, ml, o));
                float mNew = fmaxf(mOld, ml);
                float p0 = __expf(s2[i][0] - mNew);
                float p1 = __expf(s2[i][1] - mNew);
                float ls = p0 + p1;
                #pragma unroll
                for (int o = 8; o; o >>= 1) ls += __shfl_xor_sync(FULL, ls, o);
                cc2[i] = __expf(mOld - mNew);
                if (kg == 0) { rL2[i] = rL2[i] * cc2[i] + ls; rM2[i] = mNew; }
                hP2[q * 32 + kg]      = __float2half_rn(p0);
                hP2[q * 32 + kg + 16] = __float2half_rn(p1);
            }
        }

        // V(c) must be complete before PV; keep K(c+1) in flight.
        if (c + 1 < nch) cp_wait1(); else cp_wait0();
        __syncthreads();    // P + V visible to all

        // ---- PV: rescale accumulators, then O += P * V ----
        #pragma unroll
        for (int i = 0; i < 4; i++) {
            #pragma unroll
            for (int j = 0; j < 4; j++) { o1[i][j] *= cc1[i]; o2[i][j] *= cc2[i]; }
        }
        #pragma unroll 2
        for (int k4 = 0; k4 < 32; k4 += 4) {
            float4 vv0 = *(const float4*)&sVb[(k4 + 0) * 64 + kg * 4];
            float4 vv1 = *(const float4*)&sVb[(k4 + 1) * 64 + kg * 4];
            float4 vv2 = *(const float4*)&sVb[(k4 + 2) * 64 + kg * 4];
            float4 vv3 = *(const float4*)&sVb[(k4 + 3) * 64 + kg * 4];
            #pragma unroll
            for (int i = 0; i < 4; i++) {
                const int q = qg * 4 + i;
                float2 pa = __half22float2(*(const __half2*)&hP1[q * 32 + k4]);
                float2 pb = __half22float2(*(const __half2*)&hP1[q * 32 + k4 + 2]);
                float2 pc = __half22float2(*(const __half2*)&hP2[q * 32 + k4]);
                float2 pd = __half22float2(*(const __half2*)&hP2[q * 32 + k4 + 2]);
                o1[i][0] += pa.x * vv0.x + pa.y * vv1.x + pb.x * vv2.x + pb.y * vv3.x;
                o1[i][1] += pa.x * vv0.y + pa.y * vv1.y + pb.x * vv2.y + pb.y * vv3.y;
                o1[i][2] += pa.x * vv0.z + pa.y * vv1.z + pb.x * vv2.z + pb.y * vv3.z;
                o1[i][3] += pa.x * vv0.w + pa.y * vv1.w + pb.x * vv2.w + pb.y * vv3.w;
                o2[i][0] += pc.x * vv0.x + pc.y * vv1.x + pd.x * vv2.x + pd.y * vv3.x;
                o2[i][1] += pc.x * vv0.y + pc.y * vv1.y + pd.x * vv2.y + pd.y * vv3.y;
                o2[i][2] += pc.x * vv0.z + pc.y * vv1.z + pd.x * vv2.z + pd.y * vv3.z;
                o2[i][3] += pc.x * vv0.w + pc.y * vv1.w + pd.x * vv2.w + pd.y * vv3.w;
            }
        }
        // no trailing sync: next iteration starts with wait + syncthreads
    }

    // ---- epilogue: diff, RMS norm over 64 dims, weight, scale ----
    const float lam = g_lambda;
    const float4 wv = *(const float4*)&rms_w[kg * 4];
    #pragma unroll
    for (int i = 0; i < 4; i++) {
        const int q = qg * 4 + i;
        float l1 = __shfl_sync(FULL, rL1[i], src0);
        float l2 = __shfl_sync(FULL, rL2[i], src0);
        float inv1 = 1.f / l1;
        float inv2 = lam / l2;
        float a0 = o1[i][0] * inv1 - o2[i][0] * inv2;
        float a1 = o1[i][1] * inv1 - o2[i][1] * inv2;
        float a2 = o1[i][2] * inv1 - o2[i][2] * inv2;
        float a3 = o1[i][3] * inv1 - o2[i][3] * inv2;
        float ssq = a0 * a0 + a1 * a1 + a2 * a2 + a3 * a3;
        #pragma unroll
        for (int o = 8; o; o >>= 1) ssq += __shfl_xor_sync(FULL, ssq, o);
        float invr = rsqrtf(ssq * (1.0f / 64.0f) + 1e-6f) * ONE_MINUS_LI;
        float4 outv = { a0 * invr * wv.x, a1 * invr * wv.y,
                        a2 * invr * wv.z, a3 * invr * wv.w };
        *(float4*)&g_attn[(size_t)(rowBase + q) * 1024 + h * 64 + kg * 4] = outv;
    }
}

// ---------------------------------------------------------------------------
extern "C" void kernel_launch(void* const* d_in, const int* in_sizes, int n_in,
                              void* d_out, int out_size) {
    (void)in_sizes; (void)n_in; (void)out_size;
    const float* x   = (const float*)d_in[0];
    const float* Wq  = (const float*)d_in[1];
    const float* Wk  = (const float*)d_in[2];
    const float* Wv  = (const float*)d_in[3];
    const float* Wo  = (const float*)d_in[4];
    const float* lq1 = (const float*)d_in[5];
    const float* lk1 = (const float*)d_in[6];
    const float* lq2 = (const float*)d_in[7];
    const float* lk2 = (const float*)d_in[8];
    const float* rw  = (const float*)d_in[9];
    float* out = (float*)d_out;

    lambda_kernel<<<1, 32>>>(lq1, lk1, lq2, lk2);
    rope_tables_kernel<<<64, 256>>>();
    gemm_qkv_tc<<<dim3(16, 32), 256>>>(x, Wq, Wk, Wv);
    rope_k_kernel<<<4096, 256>>>();
    attn_kernel<<<dim3(16, 64), 256>>>(rw);
    gemm_out_tc<<<dim3(8, 32), 256>>>(Wo, out);
}